// round 16
// baseline (speedup 1.0000x reference)
#include <cuda_runtime.h>
#include <cuda_fp16.h>
#include <cuda_bf16.h>
#include <cooperative_groups.h>
namespace cg = cooperative_groups;

#define N_NODES 100000
#define N_EDGES 3200000
#define F_IN 8
#define F_HID 64
#define P_W1 0
#define P_B1 (F_IN * F_HID)          // 512
#define P_W2 (P_B1 + F_HID)          // 576
#define P_TOT (P_W2 + F_HID)         // 640
#define TB 256

// Scratch: __device__ globals (GPU DRAM; allocation-free rule)
__device__ float g_deg[N_NODES];
__device__ float g_dinv[N_NODES];
__device__ __align__(16) unsigned g_xsh[N_NODES * 4];      // dinv*x as 8 fp16
__device__ __align__(16) unsigned g_acc1h[N_NODES * 4];    // 8 fp16 accumulators/node
__device__ float g_sd[N_NODES];
__device__ float g_acc2[N_NODES];
__device__ float g_stage[P_TOT];

__constant__ float c_params[P_TOT];

__device__ __forceinline__ unsigned h2_bits(__half2 h) {
    union { __half2 h; unsigned u; } cvt; cvt.h = h; return cvt.u;
}
__device__ __forceinline__ __half2 bits_h2(unsigned u) {
    union { unsigned u; __half2 h; } cvt; cvt.u = u; return cvt.h;
}

#define PACK_F32X2(out, lo, hi) \
    asm("mov.b64 %0, {%1, %2};" : "=l"(out) : "f"(lo), "f"(hi))
#define UNPACK_F32X2(lo, hi, in) \
    asm("mov.b64 {%0, %1}, %2;" : "=f"(lo), "=f"(hi) : "l"(in))
#define FMA_F32X2(d, a, b, c) \
    asm("fma.rn.f32x2 %0, %1, %2, %3;" : "=l"(d) : "l"(a), "l"(b), "l"(c))

__device__ __forceinline__ void red_add_v4_f16x2(unsigned* p, unsigned h0, unsigned h1,
                                                 unsigned h2, unsigned h3) {
    asm volatile("red.global.add.noftz.v4.f16x2 [%0], {%1,%2,%3,%4};"
                 :: "l"(p), "r"(h0), "r"(h1), "r"(h2), "r"(h3) : "memory");
}

// pack W1|b1|W2 into contiguous staging for one constant-memory copy
__global__ void k_pack(const float* __restrict__ W1, const float* __restrict__ b1,
                       const float* __restrict__ W2) {
    int i = blockIdx.x * blockDim.x + threadIdx.x;
    if (i < P_B1) g_stage[i] = W1[i];
    else if (i < P_W2) g_stage[i] = b1[i - P_B1];
    else if (i < P_TOT) g_stage[i] = W2[i - P_W2];
}

// The whole GCN as one persistent cooperative kernel, 7 phases.
__global__ void __launch_bounds__(TB)
k_fused(const float* __restrict__ x, const int* __restrict__ ei,
        const float* __restrict__ w, const float* __restrict__ b2,
        float* __restrict__ out) {
    cg::grid_group grid = cg::this_grid();
    const int NT = gridDim.x * TB;
    const int t = blockIdx.x * TB + threadIdx.x;

    // P0: zero deg
    for (int i = t; i < N_NODES; i += NT) g_deg[i] = 0.0f;
    grid.sync();

    // P1: deg[col] += w
    for (int e = t; e < N_EDGES; e += NT)
        atomicAdd(&g_deg[ei[N_EDGES + e]], w[e]);
    grid.sync();

    // P2: dinv = rsqrt(1+deg); xsh = fp16(dinv*x); zero acc1h, acc2
    for (int i = t; i < N_NODES; i += NT) {
        float dv = rsqrtf(1.0f + g_deg[i]);
        g_dinv[i] = dv;
        const float4* xr = (const float4*)(x + (size_t)i * F_IN);
        float4 a = xr[0], b = xr[1];
        uint4 pk;
        pk.x = h2_bits(__floats2half2_rn(a.x * dv, a.y * dv));
        pk.y = h2_bits(__floats2half2_rn(a.z * dv, a.w * dv));
        pk.z = h2_bits(__floats2half2_rn(b.x * dv, b.y * dv));
        pk.w = h2_bits(__floats2half2_rn(b.z * dv, b.w * dv));
        ((uint4*)g_xsh)[i] = pk;
        ((uint4*)g_acc1h)[i] = make_uint4(0u, 0u, 0u, 0u);
        g_acc2[i] = 0.0f;
    }
    grid.sync();

    // P3: layer-1 edges: acc1[c] += w * xs[r]  (1 gather + 1 RED.128)
    for (int e = t; e < N_EDGES; e += NT) {
        int r = ei[e];
        int c = ei[N_EDGES + e];
        float we = w[e];
        uint4 u = __ldg((const uint4*)(g_xsh + (size_t)r * 4));
        float2 p0 = __half22float2(bits_h2(u.x));
        float2 p1 = __half22float2(bits_h2(u.y));
        float2 p2 = __half22float2(bits_h2(u.z));
        float2 p3 = __half22float2(bits_h2(u.w));
        unsigned h0 = h2_bits(__floats2half2_rn(we * p0.x, we * p0.y));
        unsigned h1 = h2_bits(__floats2half2_rn(we * p1.x, we * p1.y));
        unsigned h2 = h2_bits(__floats2half2_rn(we * p2.x, we * p2.y));
        unsigned h3 = h2_bits(__floats2half2_rn(we * p3.x, we * p3.y));
        red_add_v4_f16x2(g_acc1h + (size_t)c * 4, h0, h1, h2, h3);
    }
    grid.sync();

    // P4: node MLP (constant params, f-pairs via fma.rn.f32x2)
    for (int i = t; i < N_NODES; i += NT) {
        float dv = g_dinv[i];
        float dv2 = dv * dv;
        uint4 u = __ldg((const uint4*)(g_acc1h + (size_t)i * 4));
        float2 f0 = __half22float2(bits_h2(u.x));
        float2 f1 = __half22float2(bits_h2(u.y));
        float2 f2 = __half22float2(bits_h2(u.z));
        float2 f3 = __half22float2(bits_h2(u.w));
        const float4* xr = (const float4*)(x + (size_t)i * F_IN);
        float4 X0 = __ldg(xr), X1 = __ldg(xr + 1);
        float a[F_IN];
        a[0] = dv * f0.x + dv2 * X0.x;  a[1] = dv * f0.y + dv2 * X0.y;
        a[2] = dv * f1.x + dv2 * X0.z;  a[3] = dv * f1.y + dv2 * X0.w;
        a[4] = dv * f2.x + dv2 * X1.x;  a[5] = dv * f2.y + dv2 * X1.y;
        a[6] = dv * f3.x + dv2 * X1.z;  a[7] = dv * f3.y + dv2 * X1.w;

        unsigned long long apk[F_IN];
        #pragma unroll
        for (int k = 0; k < F_IN; k++) PACK_F32X2(apk[k], a[k], a[k]);

        const unsigned long long* W1p = (const unsigned long long*)(c_params + P_W1);
        const float2* b1p = (const float2*)(c_params + P_B1);
        const float*  W2  = c_params + P_W2;

        float s = 0.0f;
        #pragma unroll
        for (int fp = 0; fp < F_HID / 2; fp++) {
            float2 bb = b1p[fp];
            unsigned long long acc;
            PACK_F32X2(acc, bb.x, bb.y);
            #pragma unroll
            for (int k = 0; k < F_IN; k++)
                FMA_F32X2(acc, apk[k], W1p[k * (F_HID / 2) + fp], acc);
            float lo, hi;
            UNPACK_F32X2(lo, hi, acc);
            s = fmaf(fmaxf(lo, 0.0f), W2[2 * fp],     s);
            s = fmaf(fmaxf(hi, 0.0f), W2[2 * fp + 1], s);
        }
        g_sd[i] = dv * s;
    }
    grid.sync();

    // P5: layer-2 edges: acc2[c] += w * sd[r]
    for (int e = t; e < N_EDGES; e += NT) {
        int r = ei[e];
        int c = ei[N_EDGES + e];
        atomicAdd(&g_acc2[c], w[e] * __ldg(&g_sd[r]));
    }
    grid.sync();

    // P6: out = b2 + dinv * (acc2 + sd)  (float4)
    {
        float bb = b2[0];
        for (int i = t * 4; i < N_NODES; i += NT * 4) {
            float4 dv = *(const float4*)(g_dinv + i);
            float4 a2 = *(const float4*)(g_acc2 + i);
            float4 sd = *(const float4*)(g_sd + i);
            float4 o;
            o.x = bb + dv.x * (a2.x + sd.x);
            o.y = bb + dv.y * (a2.y + sd.y);
            o.z = bb + dv.z * (a2.z + sd.z);
            o.w = bb + dv.w * (a2.w + sd.w);
            *(float4*)(out + i) = o;
        }
    }
}

extern "C" void kernel_launch(void* const* d_in, const int* in_sizes, int n_in,
                              void* d_out, int out_size) {
    const float* x  = (const float*)d_in[0];
    const int*   ei = (const int*)d_in[1];     // int32 (JAX x64 disabled)
    const float* w  = (const float*)d_in[2];
    const float* W1 = (const float*)d_in[3];
    const float* b1 = (const float*)d_in[4];
    const float* W2 = (const float*)d_in[5];
    const float* b2 = (const float*)d_in[6];
    float* out = (float*)d_out;

    // 1) pack params + one D2D copy into __constant__
    k_pack<<<(P_TOT + TB - 1) / TB, TB>>>(W1, b1, W2);
    void* cparams_ptr = nullptr;
    void* stage_ptr = nullptr;
    cudaGetSymbolAddress(&cparams_ptr, c_params);
    cudaGetSymbolAddress(&stage_ptr, g_stage);
    cudaMemcpyAsync(cparams_ptr, stage_ptr, P_TOT * sizeof(float), cudaMemcpyDeviceToDevice);

    // 2) one persistent cooperative kernel for everything else
    int occ = 0;
    cudaOccupancyMaxActiveBlocksPerMultiprocessor(&occ, (const void*)k_fused, TB, 0);
    if (occ < 1) occ = 1;
    int nsm = 0;
    cudaDeviceGetAttribute(&nsm, cudaDevAttrMultiProcessorCount, 0);
    if (nsm < 1) nsm = 148;
    dim3 grid(occ * nsm), block(TB);
    void* args[] = { (void*)&x, (void*)&ei, (void*)&w, (void*)&b2, (void*)&out };
    cudaLaunchCooperativeKernel((const void*)k_fused, grid, block, args, 0, (cudaStream_t)0);
}

// round 17
// speedup vs baseline: 1.3754x; 1.3754x over previous
#include <cuda_runtime.h>
#include <cuda_fp16.h>
#include <cuda_bf16.h>

#define N_NODES 100000
#define N_EDGES 3200000
#define F_IN 8
#define F_HID 64
#define P_W1 0
#define P_B1 (F_IN * F_HID)          // 512
#define P_W2 (P_B1 + F_HID)          // 576
#define P_TOT (P_W2 + F_HID)         // 640
#define TB 256

// Scratch: __device__ globals (GPU DRAM; allocation-free rule)
__device__ float g_deg[N_NODES];
__device__ float g_dinv[N_NODES];
__device__ __align__(16) unsigned g_xsh[N_NODES * 4];      // dinv*x as 8 fp16
__device__ __align__(16) unsigned g_acc1h[N_NODES * 4];    // 8 fp16 accumulators/node
__device__ float g_sd[N_NODES];
__device__ float g_acc2[N_NODES];
__device__ float g_stage[P_TOT];

__constant__ float c_params[P_TOT];

__device__ __forceinline__ unsigned h2_bits(__half2 h) {
    union { __half2 h; unsigned u; } cvt; cvt.h = h; return cvt.u;
}
__device__ __forceinline__ __half2 bits_h2(unsigned u) {
    union { unsigned u; __half2 h; } cvt; cvt.u = u; return cvt.h;
}

#define PACK_F32X2(out, lo, hi) \
    asm("mov.b64 %0, {%1, %2};" : "=l"(out) : "f"(lo), "f"(hi))
#define UNPACK_F32X2(lo, hi, in) \
    asm("mov.b64 {%0, %1}, %2;" : "=f"(lo), "=f"(hi) : "l"(in))
#define FMA_F32X2(d, a, b, c) \
    asm("fma.rn.f32x2 %0, %1, %2, %3;" : "=l"(d) : "l"(a), "l"(b), "l"(c))

__device__ __forceinline__ void red_add_v4_f16x2(unsigned* p, unsigned h0, unsigned h1,
                                                 unsigned h2, unsigned h3) {
    asm volatile("red.global.add.noftz.v4.f16x2 [%0], {%1,%2,%3,%4};"
                 :: "l"(p), "r"(h0), "r"(h1), "r"(h2), "r"(h3) : "memory");
}

// ---------------------------------------------------------------------------
// 0) prep: zero deg + pack W1|b1|W2 into staging (no PDL: first kernel)
__global__ void k_prep(const float* __restrict__ W1, const float* __restrict__ b1,
                       const float* __restrict__ W2) {
    int i = blockIdx.x * blockDim.x + threadIdx.x;
    if (i < N_NODES) g_deg[i] = 0.0f;
    if (i < P_B1) g_stage[i] = W1[i];
    else if (i < P_W2) g_stage[i] = b1[i - P_B1];
    else if (i < P_TOT) g_stage[i] = W2[i - P_W2];
}

// 1) deg accumulate: independent stream loads, then sync, then atomic
__global__ void k_deg_acc(const int* __restrict__ ei, const float* __restrict__ w) {
    int e = blockIdx.x * blockDim.x + threadIdx.x;
    if (e < N_EDGES) {
        int c = ei[N_EDGES + e];
        float we = w[e];
        cudaGridDependencySynchronize();     // wait: g_deg zeroed
        atomicAdd(&g_deg[c], we);
    } else {
        cudaGridDependencySynchronize();
    }
}

// 2) dinv = rsqrt(1 + deg); xsh = fp16(dinv*x); zero acc1h & acc2
__global__ void k_dinv_xs(const float* __restrict__ x) {
    int i = blockIdx.x * blockDim.x + threadIdx.x;
    if (i < N_NODES) {
        const float4* xr = (const float4*)(x + (size_t)i * F_IN);
        float4 a = xr[0], b = xr[1];                   // independent of deg pass
        cudaGridDependencySynchronize();               // wait: g_deg final
        float dv = rsqrtf(1.0f + g_deg[i]);
        g_dinv[i] = dv;
        uint4 pk;
        pk.x = h2_bits(__floats2half2_rn(a.x * dv, a.y * dv));
        pk.y = h2_bits(__floats2half2_rn(a.z * dv, a.w * dv));
        pk.z = h2_bits(__floats2half2_rn(b.x * dv, b.y * dv));
        pk.w = h2_bits(__floats2half2_rn(b.z * dv, b.w * dv));
        ((uint4*)g_xsh)[i] = pk;
        ((uint4*)g_acc1h)[i] = make_uint4(0u, 0u, 0u, 0u);
        g_acc2[i] = 0.0f;
    } else {
        cudaGridDependencySynchronize();
    }
}

// 3) layer-1 edges: stream loads first, sync, then gather + RED.128
__global__ void k_layer1_edges(const int* __restrict__ ei, const float* __restrict__ w) {
    int e = blockIdx.x * blockDim.x + threadIdx.x;
    if (e < N_EDGES) {
        int r = ei[e];
        int c = ei[N_EDGES + e];
        float we = w[e];
        cudaGridDependencySynchronize();               // wait: g_xsh / g_acc1h ready
        uint4 u = __ldg((const uint4*)(g_xsh + (size_t)r * 4));
        float2 p0 = __half22float2(bits_h2(u.x));
        float2 p1 = __half22float2(bits_h2(u.y));
        float2 p2 = __half22float2(bits_h2(u.z));
        float2 p3 = __half22float2(bits_h2(u.w));
        unsigned h0 = h2_bits(__floats2half2_rn(we * p0.x, we * p0.y));
        unsigned h1 = h2_bits(__floats2half2_rn(we * p1.x, we * p1.y));
        unsigned h2 = h2_bits(__floats2half2_rn(we * p2.x, we * p2.y));
        unsigned h3 = h2_bits(__floats2half2_rn(we * p3.x, we * p3.y));
        red_add_v4_f16x2(g_acc1h + (size_t)c * 4, h0, h1, h2, h3);
    } else {
        cudaGridDependencySynchronize();
    }
}

// 4) node MLP: x load independent; acc1h/dinv dependent
__global__ void k_node_mlp(const float* __restrict__ x) {
    int i = blockIdx.x * blockDim.x + threadIdx.x;
    if (i >= N_NODES) { cudaGridDependencySynchronize(); return; }

    const float4* xr = (const float4*)(x + (size_t)i * F_IN);
    float4 X0 = __ldg(xr), X1 = __ldg(xr + 1);         // independent
    cudaGridDependencySynchronize();                   // wait: g_acc1h final
    float dv = g_dinv[i];
    float dv2 = dv * dv;
    uint4 u = __ldg((const uint4*)(g_acc1h + (size_t)i * 4));
    float2 f0 = __half22float2(bits_h2(u.x));
    float2 f1 = __half22float2(bits_h2(u.y));
    float2 f2 = __half22float2(bits_h2(u.z));
    float2 f3 = __half22float2(bits_h2(u.w));
    float a[F_IN];
    a[0] = dv * f0.x + dv2 * X0.x;  a[1] = dv * f0.y + dv2 * X0.y;
    a[2] = dv * f1.x + dv2 * X0.z;  a[3] = dv * f1.y + dv2 * X0.w;
    a[4] = dv * f2.x + dv2 * X1.x;  a[5] = dv * f2.y + dv2 * X1.y;
    a[6] = dv * f3.x + dv2 * X1.z;  a[7] = dv * f3.y + dv2 * X1.w;

    unsigned long long apk[F_IN];
    #pragma unroll
    for (int k = 0; k < F_IN; k++) PACK_F32X2(apk[k], a[k], a[k]);

    const unsigned long long* W1p = (const unsigned long long*)(c_params + P_W1);
    const float2* b1p = (const float2*)(c_params + P_B1);
    const float*  W2  = c_params + P_W2;

    float s = 0.0f;
    #pragma unroll
    for (int fp = 0; fp < F_HID / 2; fp++) {
        float2 bb = b1p[fp];
        unsigned long long acc;
        PACK_F32X2(acc, bb.x, bb.y);
        #pragma unroll
        for (int k = 0; k < F_IN; k++)
            FMA_F32X2(acc, apk[k], W1p[k * (F_HID / 2) + fp], acc);
        float lo, hi;
        UNPACK_F32X2(lo, hi, acc);
        s = fmaf(fmaxf(lo, 0.0f), W2[2 * fp],     s);
        s = fmaf(fmaxf(hi, 0.0f), W2[2 * fp + 1], s);
    }
    g_sd[i] = dv * s;
}

// 5) layer-2 edges: stream loads first, sync, then gather + RED
__global__ void k_layer2_edges(const int* __restrict__ ei, const float* __restrict__ w) {
    int e = blockIdx.x * blockDim.x + threadIdx.x;
    if (e < N_EDGES) {
        int r = ei[e];
        int c = ei[N_EDGES + e];
        float we = w[e];
        cudaGridDependencySynchronize();               // wait: g_sd ready
        atomicAdd(&g_acc2[c], we * __ldg(&g_sd[r]));
    } else {
        cudaGridDependencySynchronize();
    }
}

// 6) epilogue, 4 nodes/thread
__global__ void k_out(const float* __restrict__ b2, float* __restrict__ out) {
    int t = blockIdx.x * blockDim.x + threadIdx.x;
    int i = t * 4;
    if (i >= N_NODES) { cudaGridDependencySynchronize(); return; }
    float bb = b2[0];                                  // independent
    cudaGridDependencySynchronize();                   // wait: g_acc2 final
    float4 dv = *(const float4*)(g_dinv + i);
    float4 a2 = *(const float4*)(g_acc2 + i);
    float4 sd = *(const float4*)(g_sd + i);
    float4 o;
    o.x = bb + dv.x * (a2.x + sd.x);
    o.y = bb + dv.y * (a2.y + sd.y);
    o.z = bb + dv.z * (a2.z + sd.z);
    o.w = bb + dv.w * (a2.w + sd.w);
    *(float4*)(out + i) = o;
}

// ---------------------------------------------------------------------------
template <typename... Args>
static void launch_pdl(void (*kern)(Args...), int grid, Args... args) {
    cudaLaunchConfig_t cfg = {};
    cfg.gridDim = dim3(grid);
    cfg.blockDim = dim3(TB);
    cudaLaunchAttribute attr[1];
    attr[0].id = cudaLaunchAttributeProgrammaticStreamSerialization;
    attr[0].val.programmaticStreamSerializationAllowed = 1;
    cfg.attrs = attr;
    cfg.numAttrs = 1;
    cudaLaunchKernelEx(&cfg, kern, args...);
}

extern "C" void kernel_launch(void* const* d_in, const int* in_sizes, int n_in,
                              void* d_out, int out_size) {
    const float* x  = (const float*)d_in[0];
    const int*   ei = (const int*)d_in[1];     // int32 (JAX x64 disabled)
    const float* w  = (const float*)d_in[2];
    const float* W1 = (const float*)d_in[3];
    const float* b1 = (const float*)d_in[4];
    const float* W2 = (const float*)d_in[5];
    const float* b2 = (const float*)d_in[6];
    float* out = (float*)d_out;

    const int gridN = (N_NODES + TB - 1) / TB;
    const int gridE = (N_EDGES + TB - 1) / TB;

    // 0) zero deg + pack params, then ONE D2D copy into __constant__
    k_prep<<<gridN, TB>>>(W1, b1, W2);
    void* cparams_ptr = nullptr;
    void* stage_ptr = nullptr;
    cudaGetSymbolAddress(&cparams_ptr, c_params);
    cudaGetSymbolAddress(&stage_ptr, g_stage);
    cudaMemcpyAsync(cparams_ptr, stage_ptr, P_TOT * sizeof(float), cudaMemcpyDeviceToDevice);

    launch_pdl(k_deg_acc, gridE, ei, w);
    launch_pdl(k_dinv_xs, gridN, x);
    launch_pdl(k_layer1_edges, gridE, ei, w);
    launch_pdl(k_node_mlp, gridN, x);
    launch_pdl(k_layer2_edges, gridE, ei, w);
    launch_pdl(k_out, (N_NODES / 4 + TB - 1) / TB, b2, out);
}